// round 3
// baseline (speedup 1.0000x reference)
#include <cuda_runtime.h>
#include <cstdint>

// Problem dims (fixed by the dataset)
#define BATCH 4
#define N1V   16384
#define N2V   4096
#define C1V   128
#define C2V   256
#define CINV  384      // C2 + C1 (concat order: [interp(256), features1(128)])
#define H1V   256
#define H2V   128
#define NROWS (BATCH * N1V)   // 65536

// ---------------- scratch (static device globals; no runtime allocation) ---
__device__ __align__(16) int   g_idx[NROWS * 3];
__device__ __align__(16) float g_w  [NROWS * 3];
__device__ __align__(16) float g_X  [(size_t)NROWS * CINV];  // ~100.7 MB
__device__ __align__(16) float g_H  [(size_t)NROWS * H1V];   // ~67 MB

// ---------------------------------------------------------------------------
// Kernel 1: 3-NN over xyz2 (per batch, xyz2 tile cached in shared = 48KB)
// grid: (N1/256, B), block: 256 threads, 1 query point per thread
// ---------------------------------------------------------------------------
__global__ __launch_bounds__(256) void knn_kernel(
    const float* __restrict__ xyz1, const float* __restrict__ xyz2)
{
    __shared__ float sx[N2V];
    __shared__ float sy[N2V];
    __shared__ float sz[N2V];

    const int b = blockIdx.y;
    const float* p2 = xyz2 + (size_t)b * N2V * 3;
    for (int i = threadIdx.x; i < N2V; i += blockDim.x) {
        sx[i] = p2[3 * i + 0];
        sy[i] = p2[3 * i + 1];
        sz[i] = p2[3 * i + 2];
    }
    __syncthreads();

    const int n   = blockIdx.x * blockDim.x + threadIdx.x;
    const int row = b * N1V + n;
    const float x1 = xyz1[(size_t)row * 3 + 0];
    const float y1 = xyz1[(size_t)row * 3 + 1];
    const float z1 = xyz1[(size_t)row * 3 + 2];

    float d0 = 1e30f, d1 = 1e30f, d2 = 1e30f;
    int   i0 = 0,     i1 = 0,     i2 = 0;

    #pragma unroll 4
    for (int j = 0; j < N2V; j++) {
        const float dx = x1 - sx[j];
        const float dy = y1 - sy[j];
        const float dz = z1 - sz[j];
        const float d  = fmaf(dz, dz, fmaf(dy, dy, dx * dx));
        if (d < d2) {
            if (d < d1) {
                d2 = d1; i2 = i1;
                if (d < d0) { d1 = d0; i1 = i0; d0 = d; i0 = j; }
                else        { d1 = d;  i1 = j; }
            } else { d2 = d; i2 = j; }
        }
    }

    d0 = fmaxf(d0, 1e-10f);
    d1 = fmaxf(d1, 1e-10f);
    d2 = fmaxf(d2, 1e-10f);
    float w0 = 1.0f / d0, w1 = 1.0f / d1, w2 = 1.0f / d2;
    const float inv = 1.0f / (w0 + w1 + w2);

    g_idx[row * 3 + 0] = i0;
    g_idx[row * 3 + 1] = i1;
    g_idx[row * 3 + 2] = i2;
    g_w[row * 3 + 0] = w0 * inv;
    g_w[row * 3 + 1] = w1 * inv;
    g_w[row * 3 + 2] = w2 * inv;
}

// ---------------------------------------------------------------------------
// Kernel 2: X[row] = concat( sum_k w_k * features2[b, idx_k, :],  features1[row] )
// grid: NROWS blocks, 128 threads
// ---------------------------------------------------------------------------
__global__ __launch_bounds__(128) void build_x_kernel(
    const float* __restrict__ f1, const float* __restrict__ f2)
{
    const int row = blockIdx.x;
    const int b   = row >> 14;           // row / N1
    const int t   = threadIdx.x;

    const int   i0 = g_idx[row * 3 + 0];
    const int   i1 = g_idx[row * 3 + 1];
    const int   i2 = g_idx[row * 3 + 2];
    const float w0 = g_w[row * 3 + 0];
    const float w1 = g_w[row * 3 + 1];
    const float w2 = g_w[row * 3 + 2];

    const float* fb = f2 + (size_t)b * N2V * C2V;
    const float* p0 = fb + (size_t)i0 * C2V;
    const float* p1 = fb + (size_t)i1 * C2V;
    const float* p2 = fb + (size_t)i2 * C2V;

    float* xr = g_X + (size_t)row * CINV;
    #pragma unroll
    for (int c = t; c < C2V; c += 128) {
        xr[c] = w0 * p0[c] + w1 * p1[c] + w2 * p2[c];
    }
    xr[C2V + t] = f1[(size_t)row * C1V + t];
}

// ---------------------------------------------------------------------------
// Kernel 3/4: SGEMM  C = relu(A[M,K] * B[K,N] + bias[N])
// BM=BN=128, BK=16, 256 threads, 8x8 microtile per thread
// Requires: M%128==0, N%128==0, K%16==0 (holds for both calls)
// ---------------------------------------------------------------------------
__global__ __launch_bounds__(256) void sgemm_bias_relu(
    int M, int N, int K,
    const float* __restrict__ A, const float* __restrict__ Bm,
    const float* __restrict__ bias, float* __restrict__ C)
{
    constexpr int BM = 128, BN = 128, BK = 16, TM = 8, TN = 8;
    __shared__ float As[BK][BM];
    __shared__ float Bs[BK][BN];

    const int tid = threadIdx.x;
    const int tx  = tid & 15;       // 0..15  (N direction)
    const int ty  = tid >> 4;       // 0..15  (M direction)
    const int cRow = blockIdx.y * BM;
    const int cCol = blockIdx.x * BN;

    const float* Ap = A + (size_t)cRow * K;
    const float* Bp = Bm + cCol;

    float acc[TM][TN] = {};

    const int aRow = tid >> 2;        // 0..63
    const int aCol = (tid & 3) << 2;  // 0,4,8,12
    const int bRow = tid >> 5;        // 0..7
    const int bCol = (tid & 31) << 2; // 0..124

    for (int k0 = 0; k0 < K; k0 += BK) {
        #pragma unroll
        for (int r = 0; r < BM; r += 64) {
            float4 v = *(const float4*)(Ap + (size_t)(aRow + r) * K + k0 + aCol);
            As[aCol + 0][aRow + r] = v.x;
            As[aCol + 1][aRow + r] = v.y;
            As[aCol + 2][aRow + r] = v.z;
            As[aCol + 3][aRow + r] = v.w;
        }
        #pragma unroll
        for (int r = 0; r < BK; r += 8) {
            *(float4*)&Bs[bRow + r][bCol] =
                *(const float4*)(Bp + (size_t)(k0 + bRow + r) * N + bCol);
        }
        __syncthreads();

        #pragma unroll
        for (int k = 0; k < BK; k++) {
            float ra[TM], rb[TN];
            *(float4*)(ra + 0) = *(const float4*)&As[k][ty * TM + 0];
            *(float4*)(ra + 4) = *(const float4*)&As[k][ty * TM + 4];
            *(float4*)(rb + 0) = *(const float4*)&Bs[k][tx * TN + 0];
            *(float4*)(rb + 4) = *(const float4*)&Bs[k][tx * TN + 4];
            #pragma unroll
            for (int i = 0; i < TM; i++)
                #pragma unroll
                for (int j = 0; j < TN; j++)
                    acc[i][j] = fmaf(ra[i], rb[j], acc[i][j]);
        }
        __syncthreads();
    }

    #pragma unroll
    for (int i = 0; i < TM; i++) {
        float ov[TN];
        #pragma unroll
        for (int j = 0; j < TN; j++) {
            float v = acc[i][j] + bias[cCol + tx * TN + j];
            ov[j] = fmaxf(v, 0.0f);
        }
        float* cp = C + (size_t)(cRow + ty * TM + i) * N + cCol + tx * TN;
        *(float4*)(cp + 0) = *(float4*)(ov + 0);
        *(float4*)(cp + 4) = *(float4*)(ov + 4);
    }
}

// ---------------------------------------------------------------------------
extern "C" void kernel_launch(void* const* d_in, const int* in_sizes, int n_in,
                              void* d_out, int out_size)
{
    const float* xyz1 = (const float*)d_in[0];
    const float* xyz2 = (const float*)d_in[1];
    const float* f1   = (const float*)d_in[2];
    const float* f2   = (const float*)d_in[3];
    const float* W1   = (const float*)d_in[4];
    const float* b1   = (const float*)d_in[5];
    const float* W2   = (const float*)d_in[6];
    const float* b2   = (const float*)d_in[7];
    float* out = (float*)d_out;

    float* pX = nullptr;
    float* pH = nullptr;
    cudaGetSymbolAddress((void**)&pX, g_X);
    cudaGetSymbolAddress((void**)&pH, g_H);

    knn_kernel<<<dim3(N1V / 256, BATCH), 256>>>(xyz1, xyz2);
    build_x_kernel<<<NROWS, 128>>>(f1, f2);
    sgemm_bias_relu<<<dim3(H1V / 128, NROWS / 128), 256>>>(
        NROWS, H1V, CINV, pX, W1, b1, pH);
    sgemm_bias_relu<<<dim3(H2V / 128, NROWS / 128), 256>>>(
        NROWS, H2V, H1V, pH, W2, b2, out);
}

// round 4
// speedup vs baseline: 1.0280x; 1.0280x over previous
#include <cuda_runtime.h>
#include <cstdint>

// Problem dims (fixed by the dataset)
#define BATCH 4
#define N1V   16384
#define N2V   4096
#define C1V   128
#define C2V   256
#define CINV  384      // C2 + C1 (concat order: [interp(256), features1(128)])
#define H1V   256
#define H2V   128
#define NROWS (BATCH * N1V)   // 65536

// ---------------- scratch (static device globals; no runtime allocation) ---
__device__ __align__(16) int   g_idx[NROWS * 3];
__device__ __align__(16) float g_w  [NROWS * 3];
__device__ __align__(16) float g_X  [(size_t)NROWS * CINV];  // ~100.7 MB
__device__ __align__(16) float g_H  [(size_t)NROWS * H1V];   // ~67 MB

// ---------------- packed f32x2 helpers (sm_100+: FFMA2 path, 2x fp32 rate) --
__device__ __forceinline__ unsigned long long dup_f32x2(float x) {
    unsigned long long r;
    asm("mov.b64 %0, {%1, %1};" : "=l"(r) : "f"(x));
    return r;
}
__device__ __forceinline__ unsigned long long fma_f32x2(
    unsigned long long a, unsigned long long b, unsigned long long c) {
    unsigned long long d;
    asm("fma.rn.f32x2 %0, %1, %2, %3;" : "=l"(d) : "l"(a), "l"(b), "l"(c));
    return d;
}
__device__ __forceinline__ void unpack_f32x2(unsigned long long v, float& lo, float& hi) {
    asm("mov.b64 {%0, %1}, %2;" : "=f"(lo), "=f"(hi) : "l"(v));
}

// ---------------------------------------------------------------------------
// Kernel 1: 3-NN over xyz2. xyz2 cached as float4 in 64KB dynamic shared
// (1 LDS.128 per candidate instead of 3 scalar LDS).
// grid: (N1/256, B), block: 256 threads, 1 query point per thread
// ---------------------------------------------------------------------------
__global__ __launch_bounds__(256) void knn_kernel(
    const float* __restrict__ xyz1, const float* __restrict__ xyz2)
{
    extern __shared__ float4 s2[];   // N2V float4 = 64KB

    const int b = blockIdx.y;
    const float* p2 = xyz2 + (size_t)b * N2V * 3;
    for (int i = threadIdx.x; i < N2V; i += blockDim.x) {
        s2[i] = make_float4(p2[3 * i + 0], p2[3 * i + 1], p2[3 * i + 2], 0.0f);
    }
    __syncthreads();

    const int n   = blockIdx.x * blockDim.x + threadIdx.x;
    const int row = b * N1V + n;
    const float x1 = xyz1[(size_t)row * 3 + 0];
    const float y1 = xyz1[(size_t)row * 3 + 1];
    const float z1 = xyz1[(size_t)row * 3 + 2];

    float d0 = 1e30f, d1 = 1e30f, d2 = 1e30f;
    int   i0 = 0,     i1 = 0,     i2 = 0;

    #pragma unroll 8
    for (int j = 0; j < N2V; j++) {
        const float4 q = s2[j];
        const float dx = x1 - q.x;
        const float dy = y1 - q.y;
        const float dz = z1 - q.z;
        const float d  = fmaf(dz, dz, fmaf(dy, dy, dx * dx));
        if (d < d2) {
            if (d < d1) {
                d2 = d1; i2 = i1;
                if (d < d0) { d1 = d0; i1 = i0; d0 = d; i0 = j; }
                else        { d1 = d;  i1 = j; }
            } else { d2 = d; i2 = j; }
        }
    }

    d0 = fmaxf(d0, 1e-10f);
    d1 = fmaxf(d1, 1e-10f);
    d2 = fmaxf(d2, 1e-10f);
    float w0 = 1.0f / d0, w1 = 1.0f / d1, w2 = 1.0f / d2;
    const float inv = 1.0f / (w0 + w1 + w2);

    g_idx[row * 3 + 0] = i0;
    g_idx[row * 3 + 1] = i1;
    g_idx[row * 3 + 2] = i2;
    g_w[row * 3 + 0] = w0 * inv;
    g_w[row * 3 + 1] = w1 * inv;
    g_w[row * 3 + 2] = w2 * inv;
}

// ---------------------------------------------------------------------------
// Kernel 2: X[row] = concat( sum_k w_k * features2[b, idx_k, :],  features1[row] )
// One warp per row, float4 vectorized (f2 gathers are L2-resident).
// ---------------------------------------------------------------------------
__global__ __launch_bounds__(256) void build_x_kernel(
    const float* __restrict__ f1, const float* __restrict__ f2)
{
    const int gtid = blockIdx.x * blockDim.x + threadIdx.x;
    const int row  = gtid >> 5;           // one warp per row
    const int lane = gtid & 31;
    if (row >= NROWS) return;
    const int b = row >> 14;              // row / N1

    const int   i0 = g_idx[row * 3 + 0];
    const int   i1 = g_idx[row * 3 + 1];
    const int   i2 = g_idx[row * 3 + 2];
    const float w0 = g_w[row * 3 + 0];
    const float w1 = g_w[row * 3 + 1];
    const float w2 = g_w[row * 3 + 2];

    const float4* fb = (const float4*)(f2 + (size_t)b * N2V * C2V);
    const float4* p0 = fb + (size_t)i0 * (C2V / 4);
    const float4* p1 = fb + (size_t)i1 * (C2V / 4);
    const float4* p2 = fb + (size_t)i2 * (C2V / 4);

    float4* xr = (float4*)(g_X + (size_t)row * CINV);
    #pragma unroll
    for (int c = lane; c < C2V / 4; c += 32) {
        const float4 a = p0[c];
        const float4 bb = p1[c];
        const float4 cc = p2[c];
        float4 o;
        o.x = fmaf(w2, cc.x, fmaf(w1, bb.x, w0 * a.x));
        o.y = fmaf(w2, cc.y, fmaf(w1, bb.y, w0 * a.y));
        o.z = fmaf(w2, cc.z, fmaf(w1, bb.z, w0 * a.z));
        o.w = fmaf(w2, cc.w, fmaf(w1, bb.w, w0 * a.w));
        xr[c] = o;
    }
    // copy features1 (128 floats = 32 float4, one per lane)
    const float4* f1r = (const float4*)(f1 + (size_t)row * C1V);
    xr[C2V / 4 + lane] = f1r[lane];
}

// ---------------------------------------------------------------------------
// Kernel 3/4: SGEMM  C = relu(A[M,K] * B[K,N] + bias[N])
// BM=BN=128, BK=16, 256 threads, 8x8 microtile, inner product via FFMA2
// (packed f32x2 — 2x fp32 rate vs scalar FFMA, bit-exact rounding).
// Requires: M%128==0, N%128==0, K%16==0 (holds for both calls)
// ---------------------------------------------------------------------------
__global__ __launch_bounds__(256) void sgemm_bias_relu(
    int M, int N, int K,
    const float* __restrict__ A, const float* __restrict__ Bm,
    const float* __restrict__ bias, float* __restrict__ C)
{
    constexpr int BM = 128, BN = 128, BK = 16, TM = 8, TN = 8;
    __shared__ float As[BK][BM];
    __shared__ float Bs[BK][BN];

    const int tid = threadIdx.x;
    const int tx  = tid & 15;       // 0..15  (N direction)
    const int ty  = tid >> 4;       // 0..15  (M direction)
    const int cRow = blockIdx.y * BM;
    const int cCol = blockIdx.x * BN;

    const float* Ap = A + (size_t)cRow * K;
    const float* Bp = Bm + cCol;

    // packed accumulators: acc2[i][j2] holds columns (2*j2, 2*j2+1)
    unsigned long long acc2[TM][TN / 2] = {};

    const int aRow = tid >> 2;        // 0..63
    const int aCol = (tid & 3) << 2;  // 0,4,8,12
    const int bRow = tid >> 5;        // 0..7
    const int bCol = (tid & 31) << 2; // 0..124

    for (int k0 = 0; k0 < K; k0 += BK) {
        #pragma unroll
        for (int r = 0; r < BM; r += 64) {
            float4 v = *(const float4*)(Ap + (size_t)(aRow + r) * K + k0 + aCol);
            As[aCol + 0][aRow + r] = v.x;
            As[aCol + 1][aRow + r] = v.y;
            As[aCol + 2][aRow + r] = v.z;
            As[aCol + 3][aRow + r] = v.w;
        }
        #pragma unroll
        for (int r = 0; r < BK; r += 8) {
            *(float4*)&Bs[bRow + r][bCol] =
                *(const float4*)(Bp + (size_t)(k0 + bRow + r) * N + bCol);
        }
        __syncthreads();

        #pragma unroll
        for (int k = 0; k < BK; k++) {
            float ra[TM];
            *(float4*)(ra + 0) = *(const float4*)&As[k][ty * TM + 0];
            *(float4*)(ra + 4) = *(const float4*)&As[k][ty * TM + 4];
            // B values: 8 consecutive floats -> 4 packed f32x2 (16B aligned)
            unsigned long long rb2[TN / 2];
            *(float4*)(rb2 + 0) = *(const float4*)&Bs[k][tx * TN + 0];
            *(float4*)(rb2 + 2) = *(const float4*)&Bs[k][tx * TN + 4];
            #pragma unroll
            for (int i = 0; i < TM; i++) {
                const unsigned long long ra2 = dup_f32x2(ra[i]);
                #pragma unroll
                for (int j2 = 0; j2 < TN / 2; j2++)
                    acc2[i][j2] = fma_f32x2(ra2, rb2[j2], acc2[i][j2]);
            }
        }
        __syncthreads();
    }

    #pragma unroll
    for (int i = 0; i < TM; i++) {
        float ov[TN];
        #pragma unroll
        for (int j2 = 0; j2 < TN / 2; j2++) {
            float lo, hi;
            unpack_f32x2(acc2[i][j2], lo, hi);
            ov[2 * j2 + 0] = fmaxf(lo + bias[cCol + tx * TN + 2 * j2 + 0], 0.0f);
            ov[2 * j2 + 1] = fmaxf(hi + bias[cCol + tx * TN + 2 * j2 + 1], 0.0f);
        }
        float* cp = C + (size_t)(cRow + ty * TM + i) * N + cCol + tx * TN;
        *(float4*)(cp + 0) = *(float4*)(ov + 0);
        *(float4*)(cp + 4) = *(float4*)(ov + 4);
    }
}

// ---------------------------------------------------------------------------
extern "C" void kernel_launch(void* const* d_in, const int* in_sizes, int n_in,
                              void* d_out, int out_size)
{
    const float* xyz1 = (const float*)d_in[0];
    const float* xyz2 = (const float*)d_in[1];
    const float* f1   = (const float*)d_in[2];
    const float* f2   = (const float*)d_in[3];
    const float* W1   = (const float*)d_in[4];
    const float* b1   = (const float*)d_in[5];
    const float* W2   = (const float*)d_in[6];
    const float* b2   = (const float*)d_in[7];
    float* out = (float*)d_out;

    float* pX = nullptr;
    float* pH = nullptr;
    cudaGetSymbolAddress((void**)&pX, g_X);
    cudaGetSymbolAddress((void**)&pH, g_H);

    // 64KB dynamic shared for knn (xyz2 as float4)
    const int knn_smem = N2V * sizeof(float4);
    static bool attr_set = false;
    if (!attr_set) {
        cudaFuncSetAttribute(knn_kernel,
                             cudaFuncAttributeMaxDynamicSharedMemorySize, knn_smem);
        attr_set = true;
    }

    knn_kernel<<<dim3(N1V / 256, BATCH), 256, knn_smem>>>(xyz1, xyz2);
    build_x_kernel<<<(NROWS * 32) / 256, 256>>>(f1, f2);
    sgemm_bias_relu<<<dim3(H1V / 128, NROWS / 128), 256>>>(
        NROWS, H1V, CINV, pX, W1, b1, pH);
    sgemm_bias_relu<<<dim3(H2V / 128, NROWS / 128), 256>>>(
        NROWS, H2V, H1V, pH, W2, b2, out);
}

// round 7
// speedup vs baseline: 1.6214x; 1.5773x over previous
#include <cuda_runtime.h>
#include <cuda_bf16.h>
#include <cstdint>

// Problem dims (fixed by the dataset)
#define BATCH 4
#define N1V   16384
#define N2V   4096
#define C1V   128
#define C2V   256
#define CINV  384      // C2 + C1 (concat order: [interp(256), features1(128)])
#define H1V   256
#define H2V   128
#define NROWS (BATCH * N1V)   // 65536

// ---------------- scratch (static device globals; no runtime allocation) ---
__device__ __align__(16) int            g_idx [NROWS * 3];
__device__ __align__(16) float          g_w   [NROWS * 3];
__device__ __align__(16) __nv_bfloat16  g_Xhi [(size_t)NROWS * CINV];
__device__ __align__(16) __nv_bfloat16  g_Xlo [(size_t)NROWS * CINV];
__device__ __align__(16) __nv_bfloat16  g_Hhi [(size_t)NROWS * H1V];
__device__ __align__(16) __nv_bfloat16  g_Hlo [(size_t)NROWS * H1V];
__device__ __align__(16) __nv_bfloat16  g_W1hi[H1V * CINV];   // [h][c] K-major
__device__ __align__(16) __nv_bfloat16  g_W1lo[H1V * CINV];
__device__ __align__(16) __nv_bfloat16  g_W2hi[H2V * H1V];    // [o][h] K-major
__device__ __align__(16) __nv_bfloat16  g_W2lo[H2V * H1V];

// ---------------------------- PTX helpers (sm_80-era, legal on sm_103) -----
__device__ __forceinline__ uint32_t smem_u32(const void* p) {
    return (uint32_t)__cvta_generic_to_shared(p);
}
__device__ __forceinline__ void cp_async16(uint32_t dst, const void* src) {
    asm volatile("cp.async.ca.shared.global [%0], [%1], 16;"
                 :: "r"(dst), "l"(src) : "memory");
}
__device__ __forceinline__ void cp_commit() {
    asm volatile("cp.async.commit_group;" ::: "memory");
}
template<int N>
__device__ __forceinline__ void cp_wait() {
    asm volatile("cp.async.wait_group %0;" :: "n"(N) : "memory");
}
__device__ __forceinline__ void ldsm_x4(uint32_t* r, uint32_t addr) {
    asm volatile("ldmatrix.sync.aligned.m8n8.x4.shared.b16 {%0,%1,%2,%3}, [%4];"
                 : "=r"(r[0]), "=r"(r[1]), "=r"(r[2]), "=r"(r[3]) : "r"(addr));
}
__device__ __forceinline__ void mma_bf16(float* d, const uint32_t* a, const uint32_t* b) {
    asm volatile(
        "mma.sync.aligned.m16n8k16.row.col.f32.bf16.bf16.f32 "
        "{%0,%1,%2,%3}, {%4,%5,%6,%7}, {%8,%9}, {%0,%1,%2,%3};"
        : "+f"(d[0]), "+f"(d[1]), "+f"(d[2]), "+f"(d[3])
        : "r"(a[0]), "r"(a[1]), "r"(a[2]), "r"(a[3]), "r"(b[0]), "r"(b[1]));
}

// bf16 split helpers
__device__ __forceinline__ uint32_t pack_bf16(float a, float b) {
    __nv_bfloat162 t = __floats2bfloat162_rn(a, b);
    return *reinterpret_cast<uint32_t*>(&t);
}
__device__ __forceinline__ float bf16_round(float v) {
    return __bfloat162float(__float2bfloat16(v));
}

// ---------------------------------------------------------------------------
// Kernel 1: 3-NN over xyz2. xyz2 cached as float4 in 64KB dynamic shared.
// ---------------------------------------------------------------------------
__global__ __launch_bounds__(256) void knn_kernel(
    const float* __restrict__ xyz1, const float* __restrict__ xyz2)
{
    extern __shared__ float4 s2[];   // N2V float4 = 64KB

    const int b = blockIdx.y;
    const float* p2 = xyz2 + (size_t)b * N2V * 3;
    for (int i = threadIdx.x; i < N2V; i += blockDim.x) {
        s2[i] = make_float4(p2[3 * i + 0], p2[3 * i + 1], p2[3 * i + 2], 0.0f);
    }
    __syncthreads();

    const int n   = blockIdx.x * blockDim.x + threadIdx.x;
    const int row = b * N1V + n;
    const float x1 = xyz1[(size_t)row * 3 + 0];
    const float y1 = xyz1[(size_t)row * 3 + 1];
    const float z1 = xyz1[(size_t)row * 3 + 2];

    float d0 = 1e30f, d1 = 1e30f, d2 = 1e30f;
    int   i0 = 0,     i1 = 0,     i2 = 0;

    #pragma unroll 8
    for (int j = 0; j < N2V; j++) {
        const float4 q = s2[j];
        const float dx = x1 - q.x;
        const float dy = y1 - q.y;
        const float dz = z1 - q.z;
        const float d  = fmaf(dz, dz, fmaf(dy, dy, dx * dx));
        if (d < d2) {
            if (d < d1) {
                d2 = d1; i2 = i1;
                if (d < d0) { d1 = d0; i1 = i0; d0 = d; i0 = j; }
                else        { d1 = d;  i1 = j; }
            } else { d2 = d; i2 = j; }
        }
    }

    d0 = fmaxf(d0, 1e-10f);
    d1 = fmaxf(d1, 1e-10f);
    d2 = fmaxf(d2, 1e-10f);
    float w0 = 1.0f / d0, w1 = 1.0f / d1, w2 = 1.0f / d2;
    const float inv = 1.0f / (w0 + w1 + w2);

    g_idx[row * 3 + 0] = i0;
    g_idx[row * 3 + 1] = i1;
    g_idx[row * 3 + 2] = i2;
    g_w[row * 3 + 0] = w0 * inv;
    g_w[row * 3 + 1] = w1 * inv;
    g_w[row * 3 + 2] = w2 * inv;
}

// ---------------------------------------------------------------------------
// Kernel 2: build X as bf16 hi/lo split:  [interp(256) | features1(128)]
// One warp per row.
// ---------------------------------------------------------------------------
__global__ __launch_bounds__(256) void build_x_kernel(
    const float* __restrict__ f1, const float* __restrict__ f2)
{
    const int gtid = blockIdx.x * blockDim.x + threadIdx.x;
    const int row  = gtid >> 5;
    const int lane = gtid & 31;
    if (row >= NROWS) return;
    const int b = row >> 14;

    const int   i0 = g_idx[row * 3 + 0];
    const int   i1 = g_idx[row * 3 + 1];
    const int   i2 = g_idx[row * 3 + 2];
    const float w0 = g_w[row * 3 + 0];
    const float w1 = g_w[row * 3 + 1];
    const float w2 = g_w[row * 3 + 2];

    const float* fb = f2 + (size_t)b * N2V * C2V;
    const float* p0 = fb + (size_t)i0 * C2V;
    const float* p1 = fb + (size_t)i1 * C2V;
    const float* p2 = fb + (size_t)i2 * C2V;

    // interp: 8 cols per lane
    const int c0 = lane * 8;
    float v[8];
    {
        float4 a0 = *(const float4*)(p0 + c0), a1 = *(const float4*)(p0 + c0 + 4);
        float4 b0 = *(const float4*)(p1 + c0), b1 = *(const float4*)(p1 + c0 + 4);
        float4 cc0 = *(const float4*)(p2 + c0), cc1 = *(const float4*)(p2 + c0 + 4);
        const float* pa = (const float*)&a0;
        const float* pb = (const float*)&b0;
        const float* pc = (const float*)&cc0;
        #pragma unroll
        for (int j = 0; j < 4; j++)
            v[j] = fmaf(w2, pc[j], fmaf(w1, pb[j], w0 * pa[j]));
        pa = (const float*)&a1; pb = (const float*)&b1; pc = (const float*)&cc1;
        #pragma unroll
        for (int j = 0; j < 4; j++)
            v[4 + j] = fmaf(w2, pc[j], fmaf(w1, pb[j], w0 * pa[j]));
    }
    uint32_t hp[4], lp[4];
    #pragma unroll
    for (int j = 0; j < 4; j++) {
        float a = v[2 * j], bb = v[2 * j + 1];
        hp[j] = pack_bf16(a, bb);
        lp[j] = pack_bf16(a - bf16_round(a), bb - bf16_round(bb));
    }
    __nv_bfloat16* xh = g_Xhi + (size_t)row * CINV;
    __nv_bfloat16* xl = g_Xlo + (size_t)row * CINV;
    *(uint4*)(xh + c0) = make_uint4(hp[0], hp[1], hp[2], hp[3]);
    *(uint4*)(xl + c0) = make_uint4(lp[0], lp[1], lp[2], lp[3]);

    // features1: 4 cols per lane
    const float4 fv = *(const float4*)(f1 + (size_t)row * C1V + lane * 4);
    uint32_t h0 = pack_bf16(fv.x, fv.y);
    uint32_t h1 = pack_bf16(fv.z, fv.w);
    uint32_t l0 = pack_bf16(fv.x - bf16_round(fv.x), fv.y - bf16_round(fv.y));
    uint32_t l1 = pack_bf16(fv.z - bf16_round(fv.z), fv.w - bf16_round(fv.w));
    *(uint2*)(xh + C2V + lane * 4) = make_uint2(h0, h1);
    *(uint2*)(xl + C2V + lane * 4) = make_uint2(l0, l1);
}

// ---------------------------------------------------------------------------
// Kernel 2b: transpose + split W1 (384x256 -> [256][384]) and W2 (256x128 -> [128][256])
// ---------------------------------------------------------------------------
__global__ __launch_bounds__(256) void prep_w_kernel(
    const float* __restrict__ W1, const float* __restrict__ W2)
{
    const int idx = blockIdx.x * blockDim.x + threadIdx.x;
    if (idx < CINV * H1V) {
        const int c = idx >> 8;      // / 256
        const int h = idx & 255;
        const float vv = W1[idx];
        g_W1hi[h * CINV + c] = __float2bfloat16(vv);
        g_W1lo[h * CINV + c] = __float2bfloat16(vv - bf16_round(vv));
    } else {
        const int j = idx - CINV * H1V;
        if (j < H1V * H2V) {
            const int c = j >> 7;    // / 128
            const int h = j & 127;
            const float vv = W2[j];
            g_W2hi[h * H1V + c] = __float2bfloat16(vv);
            g_W2lo[h * H1V + c] = __float2bfloat16(vv - bf16_round(vv));
        }
    }
}

// ---------------------------------------------------------------------------
// mma.sync split-bf16 GEMM:  C[M,NN] = relu( A[M,KK] * B[NN,KK]^T + bias )
// 3-pass: D += AhiBhi + AloBhi + AhiBlo, fp32 accumulators.
// CTA 128x128, BK=32, 8 warps (2m x 4n), warp tile 64x32, double-buffer cp.async.
// SMEM rows padded to 40 halfs (80B) -> conflict-free ldmatrix.
// Pipeline: prefetch c0->buf0, c1->buf1; loop: wait(<=1), sync, compute(buf),
// sync, issue c+2 -> buf. Groups retire in order, so wait<1> pins chunk c.
// ---------------------------------------------------------------------------
template<int NN, int KK, bool SPLITOUT>
__global__ __launch_bounds__(256) void mma_gemm_kernel(
    const __nv_bfloat16* __restrict__ Ahi_g, const __nv_bfloat16* __restrict__ Alo_g,
    const __nv_bfloat16* __restrict__ Bhi_g, const __nv_bfloat16* __restrict__ Blo_g,
    const float* __restrict__ bias,
    float* __restrict__ outF,
    __nv_bfloat16* __restrict__ outHi, __nv_bfloat16* __restrict__ outLo)
{
    constexpr int BM = 128, BK = 32;
    constexpr int NC = KK / BK;
    constexpr int LDS_H = 40;                 // padded halfs per smem row
    constexpr int ROWB  = LDS_H * 2;          // 80 bytes
    constexpr int TILE_B = 128 * ROWB;        // 10240 bytes per tile
    constexpr int STAGE_B = 4 * TILE_B;       // Ahi,Alo,Bhi,Blo

    extern __shared__ char smem[];
    const uint32_t sbase = smem_u32(smem);

    const int tid  = threadIdx.x;
    const int wid  = tid >> 5;
    const int lane = tid & 31;
    const int wm   = wid & 1;          // 0..1  (m)
    const int wn   = wid >> 1;         // 0..3  (n)
    const int cRow = blockIdx.x * BM;
    const int nOff = blockIdx.y * 128;

    const __nv_bfloat16* gA[4];
    gA[0] = Ahi_g + (size_t)cRow * KK;
    gA[1] = Alo_g + (size_t)cRow * KK;
    gA[2] = Bhi_g + (size_t)nOff * KK;
    gA[3] = Blo_g + (size_t)nOff * KK;

    // stage loader: 4 tiles x 128 rows x 32 halfs (64B = 4x16B per row)
    auto load_stage = [&](int buf, int c) {
        const uint32_t s0 = sbase + buf * STAGE_B;
        #pragma unroll
        for (int t = 0; t < 4; t++) {
            const __nv_bfloat16* g = gA[t] + c * BK;
            const uint32_t st = s0 + t * TILE_B;
            #pragma unroll
            for (int i = 0; i < 2; i++) {
                const int idx = tid + i * 256;      // 0..511
                const int r   = idx >> 2;
                const int seg = idx & 3;
                cp_async16(st + r * ROWB + seg * 16, g + (size_t)r * KK + seg * 8);
            }
        }
        cp_commit();
    };

    float acc[4][4][4] = {};   // [mt][nt][4]

    load_stage(0, 0);
    if (NC > 1) load_stage(1, 1);

    // per-lane ldmatrix base offsets
    const uint32_t aOff = (uint32_t)((wm * 64 + (lane & 15)) * ROWB + (lane >> 4) * 16);
    const uint32_t bOff = (uint32_t)((wn * 32 + ((lane >> 4) & 1) * 8 + (lane & 7)) * ROWB
                                     + ((lane >> 3) & 1) * 16);

    for (int c = 0; c < NC; c++) {
        const int buf = c & 1;
        if (c + 1 < NC) cp_wait<1>(); else cp_wait<0>();
        __syncthreads();

        const uint32_t s0   = sbase + buf * STAGE_B;
        const uint32_t sAhi = s0;
        const uint32_t sAlo = s0 + TILE_B;
        const uint32_t sBhi = s0 + 2 * TILE_B;
        const uint32_t sBlo = s0 + 3 * TILE_B;

        #pragma unroll
        for (int ks = 0; ks < 2; ks++) {
            const uint32_t kb = ks * 32;
            uint32_t ahi[4][4], alo[4][4], bhi[2][4], blo[2][4];
            #pragma unroll
            for (int mt = 0; mt < 4; mt++) {
                ldsm_x4(ahi[mt], sAhi + aOff + kb + mt * 16 * ROWB);
                ldsm_x4(alo[mt], sAlo + aOff + kb + mt * 16 * ROWB);
            }
            #pragma unroll
            for (int p = 0; p < 2; p++) {
                ldsm_x4(bhi[p], sBhi + bOff + kb + p * 16 * ROWB);
                ldsm_x4(blo[p], sBlo + bOff + kb + p * 16 * ROWB);
            }
            #pragma unroll
            for (int mt = 0; mt < 4; mt++) {
                #pragma unroll
                for (int nt = 0; nt < 4; nt++) {
                    uint32_t* bh = &bhi[nt >> 1][(nt & 1) * 2];
                    uint32_t* bl = &blo[nt >> 1][(nt & 1) * 2];
                    mma_bf16(acc[mt][nt], ahi[mt], bh);
                    mma_bf16(acc[mt][nt], alo[mt], bh);
                    mma_bf16(acc[mt][nt], ahi[mt], bl);
                }
            }
        }
        __syncthreads();
        if (c + 2 < NC) load_stage(buf, c + 2);
    }

    // ---------------- epilogue: bias + relu + store ----------------
    #pragma unroll
    for (int nt = 0; nt < 4; nt++) {
        const int col = nOff + wn * 32 + nt * 8 + (lane & 3) * 2;
        const float bz0 = bias[col];
        const float bz1 = bias[col + 1];
        #pragma unroll
        for (int mt = 0; mt < 4; mt++) {
            const int row0 = cRow + wm * 64 + mt * 16 + (lane >> 2);
            float v0 = fmaxf(acc[mt][nt][0] + bz0, 0.0f);
            float v1 = fmaxf(acc[mt][nt][1] + bz1, 0.0f);
            float v2 = fmaxf(acc[mt][nt][2] + bz0, 0.0f);
            float v3 = fmaxf(acc[mt][nt][3] + bz1, 0.0f);
            if (SPLITOUT) {
                *(uint32_t*)(outHi + (size_t)row0 * NN + col) = pack_bf16(v0, v1);
                *(uint32_t*)(outLo + (size_t)row0 * NN + col) =
                    pack_bf16(v0 - bf16_round(v0), v1 - bf16_round(v1));
                *(uint32_t*)(outHi + (size_t)(row0 + 8) * NN + col) = pack_bf16(v2, v3);
                *(uint32_t*)(outLo + (size_t)(row0 + 8) * NN + col) =
                    pack_bf16(v2 - bf16_round(v2), v3 - bf16_round(v3));
            } else {
                *(float2*)(outF + (size_t)row0 * NN + col) = make_float2(v0, v1);
                *(float2*)(outF + (size_t)(row0 + 8) * NN + col) = make_float2(v2, v3);
            }
        }
    }
}

// ---------------------------------------------------------------------------
extern "C" void kernel_launch(void* const* d_in, const int* in_sizes, int n_in,
                              void* d_out, int out_size)
{
    const float* xyz1 = (const float*)d_in[0];
    const float* xyz2 = (const float*)d_in[1];
    const float* f1   = (const float*)d_in[2];
    const float* f2   = (const float*)d_in[3];
    const float* W1   = (const float*)d_in[4];
    const float* b1   = (const float*)d_in[5];
    const float* W2   = (const float*)d_in[6];
    const float* b2   = (const float*)d_in[7];
    float* out = (float*)d_out;

    __nv_bfloat16 *pXhi, *pXlo, *pHhi, *pHlo, *pW1h, *pW1l, *pW2h, *pW2l;
    cudaGetSymbolAddress((void**)&pXhi, g_Xhi);
    cudaGetSymbolAddress((void**)&pXlo, g_Xlo);
    cudaGetSymbolAddress((void**)&pHhi, g_Hhi);
    cudaGetSymbolAddress((void**)&pHlo, g_Hlo);
    cudaGetSymbolAddress((void**)&pW1h, g_W1hi);
    cudaGetSymbolAddress((void**)&pW1l, g_W1lo);
    cudaGetSymbolAddress((void**)&pW2h, g_W2hi);
    cudaGetSymbolAddress((void**)&pW2l, g_W2lo);

    const int knn_smem  = N2V * sizeof(float4);        // 64KB
    const int gemm_smem = 2 * 4 * 128 * 80;            // 81920 bytes

    static bool attr_set = false;
    if (!attr_set) {
        cudaFuncSetAttribute(knn_kernel,
            cudaFuncAttributeMaxDynamicSharedMemorySize, knn_smem);
        cudaFuncSetAttribute(mma_gemm_kernel<H1V, CINV, true>,
            cudaFuncAttributeMaxDynamicSharedMemorySize, gemm_smem);
        cudaFuncSetAttribute(mma_gemm_kernel<H2V, H1V, false>,
            cudaFuncAttributeMaxDynamicSharedMemorySize, gemm_smem);
        attr_set = true;
    }

    knn_kernel<<<dim3(N1V / 256, BATCH), 256, knn_smem>>>(xyz1, xyz2);
    prep_w_kernel<<<(CINV * H1V + H1V * H2V) / 256, 256>>>(W1, W2);
    build_x_kernel<<<(NROWS * 32) / 256, 256>>>(f1, f2);

    mma_gemm_kernel<H1V, CINV, true>
        <<<dim3(NROWS / 128, H1V / 128), 256, gemm_smem>>>(
            pXhi, pXlo, pW1h, pW1l, b1, nullptr, pHhi, pHlo);
    mma_gemm_kernel<H2V, H1V, false>
        <<<dim3(NROWS / 128, H2V / 128), 256, gemm_smem>>>(
            pHhi, pHlo, pW2h, pW2l, b2, out, nullptr, nullptr);
}

// round 8
// speedup vs baseline: 2.0661x; 1.2743x over previous
#include <cuda_runtime.h>
#include <cuda_fp16.h>
#include <cstdint>

// Problem dims (fixed by the dataset)
#define BATCH 4
#define N1V   16384
#define N2V   4096
#define C1V   128
#define C2V   256
#define CINV  384      // C2 + C1 (concat order: [interp(256), features1(128)])
#define H1V   256
#define H2V   128
#define NROWS (BATCH * N1V)   // 65536

// ---------------- scratch (static device globals; no runtime allocation) ---
__device__ __align__(16) int     g_idx [NROWS * 3];
__device__ __align__(16) float   g_w   [NROWS * 3];
__device__ __align__(16) __half  g_Xhi [(size_t)NROWS * CINV];
__device__ __align__(16) __half  g_Xlo [(size_t)NROWS * CINV];
__device__ __align__(16) __half  g_Hhi [(size_t)NROWS * H1V];
__device__ __align__(16) __half  g_Hlo [(size_t)NROWS * H1V];
__device__ __align__(16) __half  g_W1  [H1V * CINV];   // [h][c] K-major, fp16
__device__ __align__(16) __half  g_W2  [H2V * H1V];    // [o][h] K-major, fp16

// ---------------------------- PTX helpers (sm_80-era, legal on sm_103) -----
__device__ __forceinline__ uint32_t smem_u32(const void* p) {
    return (uint32_t)__cvta_generic_to_shared(p);
}
__device__ __forceinline__ void cp_async16(uint32_t dst, const void* src) {
    asm volatile("cp.async.ca.shared.global [%0], [%1], 16;"
                 :: "r"(dst), "l"(src) : "memory");
}
__device__ __forceinline__ void cp_commit() {
    asm volatile("cp.async.commit_group;" ::: "memory");
}
template<int N>
__device__ __forceinline__ void cp_wait() {
    asm volatile("cp.async.wait_group %0;" :: "n"(N) : "memory");
}
__device__ __forceinline__ void ldsm_x4(uint32_t* r, uint32_t addr) {
    asm volatile("ldmatrix.sync.aligned.m8n8.x4.shared.b16 {%0,%1,%2,%3}, [%4];"
                 : "=r"(r[0]), "=r"(r[1]), "=r"(r[2]), "=r"(r[3]) : "r"(addr));
}
__device__ __forceinline__ void mma_fp16(float* d, const uint32_t* a, const uint32_t* b) {
    asm volatile(
        "mma.sync.aligned.m16n8k16.row.col.f32.f16.f16.f32 "
        "{%0,%1,%2,%3}, {%4,%5,%6,%7}, {%8,%9}, {%0,%1,%2,%3};"
        : "+f"(d[0]), "+f"(d[1]), "+f"(d[2]), "+f"(d[3])
        : "r"(a[0]), "r"(a[1]), "r"(a[2]), "r"(a[3]), "r"(b[0]), "r"(b[1]));
}

// fp16 split helpers
__device__ __forceinline__ uint32_t pack_half2(float a, float b) {
    __half2 t = __floats2half2_rn(a, b);
    return *reinterpret_cast<uint32_t*>(&t);
}
__device__ __forceinline__ float h_round(float v) {
    return __half2float(__float2half_rn(v));
}

// ---------------------------------------------------------------------------
// Kernel 1: 3-NN over xyz2 via score s = 0.5|p|^2 - q.p  (argmin-equivalent).
// xyz2 cached as float4 (px,py,pz, 0.5|p|^2) in 64KB dynamic shared.
// Inner loop: 1 LDS.128 + 3 FFMA + compare. d recovered as 2s + |q|^2.
// ---------------------------------------------------------------------------
__global__ __launch_bounds__(256) void knn_kernel(
    const float* __restrict__ xyz1, const float* __restrict__ xyz2)
{
    extern __shared__ float4 s2[];   // N2V float4 = 64KB

    const int b = blockIdx.y;
    const float* p2 = xyz2 + (size_t)b * N2V * 3;
    for (int i = threadIdx.x; i < N2V; i += blockDim.x) {
        const float px = p2[3 * i + 0];
        const float py = p2[3 * i + 1];
        const float pz = p2[3 * i + 2];
        const float h  = 0.5f * fmaf(pz, pz, fmaf(py, py, px * px));
        s2[i] = make_float4(px, py, pz, h);
    }
    __syncthreads();

    const int n   = blockIdx.x * blockDim.x + threadIdx.x;
    const int row = b * N1V + n;
    const float x1 = xyz1[(size_t)row * 3 + 0];
    const float y1 = xyz1[(size_t)row * 3 + 1];
    const float z1 = xyz1[(size_t)row * 3 + 2];
    const float nqx = -x1, nqy = -y1, nqz = -z1;

    float s0 = 1e30f, s1 = 1e30f, s2v = 1e30f;
    int   i0 = 0,     i1 = 0,     i2 = 0;

    #pragma unroll 8
    for (int j = 0; j < N2V; j++) {
        const float4 q = s2[j];
        const float s = fmaf(nqx, q.x, fmaf(nqy, q.y, fmaf(nqz, q.z, q.w)));
        if (s < s2v) {
            if (s < s1) {
                s2v = s1; i2 = i1;
                if (s < s0) { s1 = s0; i1 = i0; s0 = s; i0 = j; }
                else        { s1 = s;  i1 = j; }
            } else { s2v = s; i2 = j; }
        }
    }

    const float qq = fmaf(z1, z1, fmaf(y1, y1, x1 * x1));
    float d0 = fmaxf(fmaf(2.0f, s0,  qq), 1e-10f);
    float d1 = fmaxf(fmaf(2.0f, s1,  qq), 1e-10f);
    float d2 = fmaxf(fmaf(2.0f, s2v, qq), 1e-10f);
    float w0 = 1.0f / d0, w1 = 1.0f / d1, w2 = 1.0f / d2;
    const float inv = 1.0f / (w0 + w1 + w2);

    g_idx[row * 3 + 0] = i0;
    g_idx[row * 3 + 1] = i1;
    g_idx[row * 3 + 2] = i2;
    g_w[row * 3 + 0] = w0 * inv;
    g_w[row * 3 + 1] = w1 * inv;
    g_w[row * 3 + 2] = w2 * inv;
}

// ---------------------------------------------------------------------------
// Kernel 2: build X as fp16 hi/lo split:  [interp(256) | features1(128)]
// One warp per row.
// ---------------------------------------------------------------------------
__global__ __launch_bounds__(256) void build_x_kernel(
    const float* __restrict__ f1, const float* __restrict__ f2)
{
    const int gtid = blockIdx.x * blockDim.x + threadIdx.x;
    const int row  = gtid >> 5;
    const int lane = gtid & 31;
    if (row >= NROWS) return;
    const int b = row >> 14;

    const int   i0 = g_idx[row * 3 + 0];
    const int   i1 = g_idx[row * 3 + 1];
    const int   i2 = g_idx[row * 3 + 2];
    const float w0 = g_w[row * 3 + 0];
    const float w1 = g_w[row * 3 + 1];
    const float w2 = g_w[row * 3 + 2];

    const float* fb = f2 + (size_t)b * N2V * C2V;
    const float* p0 = fb + (size_t)i0 * C2V;
    const float* p1 = fb + (size_t)i1 * C2V;
    const float* p2 = fb + (size_t)i2 * C2V;

    // interp: 8 cols per lane
    const int c0 = lane * 8;
    float v[8];
    {
        float4 a0 = *(const float4*)(p0 + c0), a1 = *(const float4*)(p0 + c0 + 4);
        float4 b0 = *(const float4*)(p1 + c0), b1 = *(const float4*)(p1 + c0 + 4);
        float4 cc0 = *(const float4*)(p2 + c0), cc1 = *(const float4*)(p2 + c0 + 4);
        const float* pa = (const float*)&a0;
        const float* pb = (const float*)&b0;
        const float* pc = (const float*)&cc0;
        #pragma unroll
        for (int j = 0; j < 4; j++)
            v[j] = fmaf(w2, pc[j], fmaf(w1, pb[j], w0 * pa[j]));
        pa = (const float*)&a1; pb = (const float*)&b1; pc = (const float*)&cc1;
        #pragma unroll
        for (int j = 0; j < 4; j++)
            v[4 + j] = fmaf(w2, pc[j], fmaf(w1, pb[j], w0 * pa[j]));
    }
    uint32_t hp[4], lp[4];
    #pragma unroll
    for (int j = 0; j < 4; j++) {
        float a = v[2 * j], bb = v[2 * j + 1];
        hp[j] = pack_half2(a, bb);
        lp[j] = pack_half2(a - h_round(a), bb - h_round(bb));
    }
    __half* xh = g_Xhi + (size_t)row * CINV;
    __half* xl = g_Xlo + (size_t)row * CINV;
    *(uint4*)(xh + c0) = make_uint4(hp[0], hp[1], hp[2], hp[3]);
    *(uint4*)(xl + c0) = make_uint4(lp[0], lp[1], lp[2], lp[3]);

    // features1: 4 cols per lane
    const float4 fv = *(const float4*)(f1 + (size_t)row * C1V + lane * 4);
    uint32_t h0 = pack_half2(fv.x, fv.y);
    uint32_t h1 = pack_half2(fv.z, fv.w);
    uint32_t l0 = pack_half2(fv.x - h_round(fv.x), fv.y - h_round(fv.y));
    uint32_t l1 = pack_half2(fv.z - h_round(fv.z), fv.w - h_round(fv.w));
    *(uint2*)(xh + C2V + lane * 4) = make_uint2(h0, h1);
    *(uint2*)(xl + C2V + lane * 4) = make_uint2(l0, l1);
}

// ---------------------------------------------------------------------------
// Kernel 2b: transpose W1 (384x256 -> [256][384]) and W2 (256x128 -> [128][256])
// to K-major fp16 (single precision level — B-side quantization ~3e-4 rel).
// ---------------------------------------------------------------------------
__global__ __launch_bounds__(256) void prep_w_kernel(
    const float* __restrict__ W1, const float* __restrict__ W2)
{
    const int idx = blockIdx.x * blockDim.x + threadIdx.x;
    if (idx < CINV * H1V) {
        const int c = idx >> 8;      // / 256
        const int h = idx & 255;
        g_W1[h * CINV + c] = __float2half_rn(W1[idx]);
    } else {
        const int j = idx - CINV * H1V;
        if (j < H1V * H2V) {
            const int c = j >> 7;    // / 128
            const int h = j & 127;
            g_W2[h * H1V + c] = __float2half_rn(W2[j]);
        }
    }
}

// ---------------------------------------------------------------------------
// mma.sync split-fp16 GEMM:  C[M,NN] = relu( A[M,KK] * B[NN,KK]^T + bias )
// 2-pass: D += Ahi*B + Alo*B, fp32 accumulators. B single fp16.
// CTA 128x128, BK=32, 8 warps (2m x 4n), warp tile 64x32, double-buffer cp.async.
// SMEM rows padded to 40 halfs (80B) -> conflict-free ldmatrix.
// Pipeline: prefetch c0->buf0, c1->buf1; loop: wait(<=1), sync, compute(buf),
// sync, issue c+2 -> buf. Groups retire in order, so wait<1> pins chunk c.
// ---------------------------------------------------------------------------
template<int NN, int KK, bool SPLITOUT>
__global__ __launch_bounds__(256) void mma_gemm_kernel(
    const __half* __restrict__ Ahi_g, const __half* __restrict__ Alo_g,
    const __half* __restrict__ B_g,
    const float* __restrict__ bias,
    float* __restrict__ outF,
    __half* __restrict__ outHi, __half* __restrict__ outLo)
{
    constexpr int BM = 128, BK = 32;
    constexpr int NC = KK / BK;
    constexpr int LDS_H = 40;                 // padded halfs per smem row
    constexpr int ROWB  = LDS_H * 2;          // 80 bytes
    constexpr int TILE_B = 128 * ROWB;        // 10240 bytes per tile
    constexpr int STAGE_B = 3 * TILE_B;       // Ahi, Alo, B

    extern __shared__ char smem[];
    const uint32_t sbase = smem_u32(smem);

    const int tid  = threadIdx.x;
    const int wid  = tid >> 5;
    const int lane = tid & 31;
    const int wm   = wid & 1;          // 0..1  (m)
    const int wn   = wid >> 1;         // 0..3  (n)
    const int cRow = blockIdx.x * BM;
    const int nOff = blockIdx.y * 128;

    const __half* gA[3];
    gA[0] = Ahi_g + (size_t)cRow * KK;
    gA[1] = Alo_g + (size_t)cRow * KK;
    gA[2] = B_g   + (size_t)nOff * KK;

    // stage loader: 3 tiles x 128 rows x 32 halfs (64B = 4x16B per row)
    auto load_stage = [&](int buf, int c) {
        const uint32_t s0 = sbase + buf * STAGE_B;
        #pragma unroll
        for (int t = 0; t < 3; t++) {
            const __half* g = gA[t] + c * BK;
            const uint32_t st = s0 + t * TILE_B;
            #pragma unroll
            for (int i = 0; i < 2; i++) {
                const int idx = tid + i * 256;      // 0..511
                const int r   = idx >> 2;
                const int seg = idx & 3;
                cp_async16(st + r * ROWB + seg * 16, g + (size_t)r * KK + seg * 8);
            }
        }
        cp_commit();
    };

    float acc[4][4][4] = {};   // [mt][nt][4]

    load_stage(0, 0);
    if (NC > 1) load_stage(1, 1);

    // per-lane ldmatrix base offsets
    const uint32_t aOff = (uint32_t)((wm * 64 + (lane & 15)) * ROWB + (lane >> 4) * 16);
    const uint32_t bOff = (uint32_t)((wn * 32 + ((lane >> 4) & 1) * 8 + (lane & 7)) * ROWB
                                     + ((lane >> 3) & 1) * 16);

    for (int c = 0; c < NC; c++) {
        const int buf = c & 1;
        if (c + 1 < NC) cp_wait<1>(); else cp_wait<0>();
        __syncthreads();

        const uint32_t s0   = sbase + buf * STAGE_B;
        const uint32_t sAhi = s0;
        const uint32_t sAlo = s0 + TILE_B;
        const uint32_t sB   = s0 + 2 * TILE_B;

        #pragma unroll
        for (int ks = 0; ks < 2; ks++) {
            const uint32_t kb = ks * 32;
            uint32_t ahi[4][4], alo[4][4], bt[2][4];
            #pragma unroll
            for (int mt = 0; mt < 4; mt++) {
                ldsm_x4(ahi[mt], sAhi + aOff + kb + mt * 16 * ROWB);
                ldsm_x4(alo[mt], sAlo + aOff + kb + mt * 16 * ROWB);
            }
            #pragma unroll
            for (int p = 0; p < 2; p++) {
                ldsm_x4(bt[p], sB + bOff + kb + p * 16 * ROWB);
            }
            #pragma unroll
            for (int mt = 0; mt < 4; mt++) {
                #pragma unroll
                for (int nt = 0; nt < 4; nt++) {
                    uint32_t* bh = &bt[nt >> 1][(nt & 1) * 2];
                    mma_fp16(acc[mt][nt], ahi[mt], bh);
                    mma_fp16(acc[mt][nt], alo[mt], bh);
                }
            }
        }
        __syncthreads();
        if (c + 2 < NC) load_stage(buf, c + 2);
    }

    // ---------------- epilogue: bias + relu + store ----------------
    #pragma unroll
    for (int nt = 0; nt < 4; nt++) {
        const int col = nOff + wn * 32 + nt * 8 + (lane & 3) * 2;
        const float bz0 = bias[col];
        const float bz1 = bias[col + 1];
        #pragma unroll
        for (int mt = 0; mt < 4; mt++) {
            const int row0 = cRow + wm * 64 + mt * 16 + (lane >> 2);
            float v0 = fmaxf(acc[mt][nt][0] + bz0, 0.0f);
            float v1 = fmaxf(acc[mt][nt][1] + bz1, 0.0f);
            float v2 = fmaxf(acc[mt][nt][2] + bz0, 0.0f);
            float v3 = fmaxf(acc[mt][nt][3] + bz1, 0.0f);
            if (SPLITOUT) {
                *(uint32_t*)(outHi + (size_t)row0 * NN + col) = pack_half2(v0, v1);
                *(uint32_t*)(outLo + (size_t)row0 * NN + col) =
                    pack_half2(v0 - h_round(v0), v1 - h_round(v1));
                *(uint32_t*)(outHi + (size_t)(row0 + 8) * NN + col) = pack_half2(v2, v3);
                *(uint32_t*)(outLo + (size_t)(row0 + 8) * NN + col) =
                    pack_half2(v2 - h_round(v2), v3 - h_round(v3));
            } else {
                *(float2*)(outF + (size_t)row0 * NN + col) = make_float2(v0, v1);
                *(float2*)(outF + (size_t)(row0 + 8) * NN + col) = make_float2(v2, v3);
            }
        }
    }
}

// ---------------------------------------------------------------------------
extern "C" void kernel_launch(void* const* d_in, const int* in_sizes, int n_in,
                              void* d_out, int out_size)
{
    const float* xyz1 = (const float*)d_in[0];
    const float* xyz2 = (const float*)d_in[1];
    const float* f1   = (const float*)d_in[2];
    const float* f2   = (const float*)d_in[3];
    const float* W1   = (const float*)d_in[4];
    const float* b1   = (const float*)d_in[5];
    const float* W2   = (const float*)d_in[6];
    const float* b2   = (const float*)d_in[7];
    float* out = (float*)d_out;

    __half *pXhi, *pXlo, *pHhi, *pHlo, *pW1, *pW2;
    cudaGetSymbolAddress((void**)&pXhi, g_Xhi);
    cudaGetSymbolAddress((void**)&pXlo, g_Xlo);
    cudaGetSymbolAddress((void**)&pHhi, g_Hhi);
    cudaGetSymbolAddress((void**)&pHlo, g_Hlo);
    cudaGetSymbolAddress((void**)&pW1, g_W1);
    cudaGetSymbolAddress((void**)&pW2, g_W2);

    const int knn_smem  = N2V * sizeof(float4);        // 64KB
    const int gemm_smem = 2 * 3 * 128 * 80;            // 61440 bytes

    static bool attr_set = false;
    if (!attr_set) {
        cudaFuncSetAttribute(knn_kernel,
            cudaFuncAttributeMaxDynamicSharedMemorySize, knn_smem);
        cudaFuncSetAttribute(mma_gemm_kernel<H1V, CINV, true>,
            cudaFuncAttributeMaxDynamicSharedMemorySize, gemm_smem);
        cudaFuncSetAttribute(mma_gemm_kernel<H2V, H1V, false>,
            cudaFuncAttributeMaxDynamicSharedMemorySize, gemm_smem);
        attr_set = true;
    }

    knn_kernel<<<dim3(N1V / 256, BATCH), 256, knn_smem>>>(xyz1, xyz2);
    prep_w_kernel<<<(CINV * H1V + H1V * H2V) / 256, 256>>>(W1, W2);
    build_x_kernel<<<(NROWS * 32) / 256, 256>>>(f1, f2);

    mma_gemm_kernel<H1V, CINV, true>
        <<<dim3(NROWS / 128, H1V / 128), 256, gemm_smem>>>(
            pXhi, pXlo, pW1, b1, nullptr, pHhi, pHlo);
    mma_gemm_kernel<H2V, H1V, false>
        <<<dim3(NROWS / 128, H2V / 128), 256, gemm_smem>>>(
            pHhi, pHlo, pW2, b2, out, nullptr, nullptr);
}